// round 5
// baseline (speedup 1.0000x reference)
#include <cuda_runtime.h>

// Lag2Eul CIC deposit: x (2,4,128,128,128) f32 -> out (2,1,128,128,128) f32
// DIS_NORM = 6*512/1000 = 3.072

#define PNUM  (128*128*128)      // 2097152
#define NB    2
#define DISN  3.072f
#define RBLK  32                 // partial-sum blocks per (n,dim)

__device__ float g_part[6 * RBLK];   // overwritten every run: no zeroing needed

// grid (RBLK, 6), 256 threads. Each block sums a contiguous 1/RBLK chunk.
__global__ void __launch_bounds__(256)
reduce_partial_kernel(const float* __restrict__ x) {
    int y = blockIdx.y;                 // n*3 + dim
    int n = y / 3, c = y % 3;
    const int CHUNK4 = PNUM / 4 / RBLK; // float4 elements per block
    const float4* base = (const float4*)(x + ((size_t)n * 4 + c) * PNUM)
                       + (size_t)blockIdx.x * CHUNK4;

    float s = 0.0f;
    for (int i = threadIdx.x; i < CHUNK4; i += 256) {
        float4 v = base[i];
        s += (v.x + v.y) + (v.z + v.w);
    }
    #pragma unroll
    for (int o = 16; o > 0; o >>= 1)
        s += __shfl_down_sync(0xffffffffu, s, o);

    __shared__ float ws[8];
    if ((threadIdx.x & 31) == 0) ws[threadIdx.x >> 5] = s;
    __syncthreads();
    if (threadIdx.x < 8) {
        s = ws[threadIdx.x];
        #pragma unroll
        for (int o = 4; o > 0; o >>= 1)
            s += __shfl_down_sync(0xffu, s, o);
        if (threadIdx.x == 0) g_part[y * RBLK + blockIdx.x] = s;
    }
}

__device__ __forceinline__ void red_v2(float* p, float a, float b) {
    asm volatile("red.global.add.v2.f32 [%0], {%1, %2};"
                 :: "l"(p), "f"(a), "f"(b) : "memory");
}

// 4 lanes per particle: lane bit0 -> h corner, bit1 -> d corner.
// Each lane deposits the w-pair (t2, t2+1): one v2 RED when t2 even, else
// two scalar REDs with individual bounds checks.
__global__ void __launch_bounds__(512)
scatter_kernel(const float* __restrict__ x, float* __restrict__ out) {
    int n = blockIdx.y;

    // Redundant per-block mean finalize: warps 0-2 fold 32 partials each.
    __shared__ float smean[3];
    int wid = threadIdx.x >> 5, lid = threadIdx.x & 31;
    if (wid < 3) {
        float s = g_part[(n * 3 + wid) * RBLK + lid];
        #pragma unroll
        for (int o = 16; o > 0; o >>= 1)
            s += __shfl_down_sync(0xffffffffu, s, o);
        if (lid == 0) smean[wid] = s * (1.0f / (float)PNUM);
    }
    __syncthreads();
    float m0 = smean[0], m1 = smean[1], m2 = smean[2];

    int t = blockIdx.x * blockDim.x + threadIdx.x;   // particle*4 + corner
    int p = t >> 2;
    int corner = t & 3;

    const float* xb = x + (size_t)n * 4 * PNUM;

    int w = p & 127;
    int h = (p >> 7) & 127;
    int d = p >> 14;

    // 4 lanes share each address -> warp-broadcast loads.
    float p0 = (__ldg(xb + p)            - m0) * DISN + (float)d + 0.5f;
    float p1 = (__ldg(xb + PNUM + p)     - m1) * DISN + (float)h + 0.5f;
    float p2 = (__ldg(xb + 2 * PNUM + p) - m2) * DISN + (float)w + 0.5f;
    float v  =  __ldg(xb + 3 * PNUM + p);

    float i0 = floorf(p0), i1 = floorf(p1), i2 = floorf(p2);
    float f0 = p0 - i0, f1 = p1 - i1, f2 = p2 - i2;
    int t0 = (int)i0, t1 = (int)i1, t2 = (int)i2;

    int ch = corner & 1;
    int cd = (corner >> 1) & 1;
    int a0 = t0 + cd;
    int a1 = t1 + ch;

    if (((unsigned)a0 < 128u) & ((unsigned)a1 < 128u)) {
        float base = v * (cd ? f0 : 1.0f - f0) * (ch ? f1 : 1.0f - f1);
        float wlo = base * (1.0f - f2);
        float whi = base * f2;
        float* row = out + (size_t)n * PNUM + (a0 << 14) + (a1 << 7);

        if (((t2 & 1) == 0) & ((unsigned)t2 < 127u)) {
            // even t2: both cells valid, 8B-aligned -> one packed RED
            red_v2(row + t2, wlo, whi);
        } else {
            if ((unsigned)t2 < 128u)        atomicAdd(row + t2,     wlo);
            if ((unsigned)(t2 + 1) < 128u)  atomicAdd(row + t2 + 1, whi);
        }
    }
}

extern "C" void kernel_launch(void* const* d_in, const int* in_sizes, int n_in,
                              void* d_out, int out_size) {
    const float* x = (const float*)d_in[0];
    float* out = (float*)d_out;

    cudaMemsetAsync(out, 0, (size_t)out_size * sizeof(float));

    dim3 rgrid(RBLK, 6);
    reduce_partial_kernel<<<rgrid, 256>>>(x);

    dim3 sgrid((PNUM * 4) / 512, NB);
    scatter_kernel<<<sgrid, 512>>>(x, out);
}